// round 3
// baseline (speedup 1.0000x reference)
#include <cuda_runtime.h>

#define NN   5000
#define EE   80000
#define HH   32
#define BB   16
#define BH   512      // B*H
#define FEAT 47
#define EPB  4        // edges per block (1 warp each)

// ---- scratch (static __device__: allocation-free per harness rules) ----
__device__ float g_ex[(size_t)EE * BH];      // per-edge exp(alpha) [E,B,H]
__device__ int   g_cnt[NN];
__device__ int   g_off[NN + 1];
__device__ int   g_cur[NN];
__device__ int   g_eidx[EE];
__device__ int   g_esrc[EE];

__device__ __forceinline__ float sigmoidf(float x) {
    return 1.f / (1.f + __expf(-x));
}
__device__ __forceinline__ float lrelu(float x) {
    return x > 0.f ? x : 0.01f * x;
}

// ---------------- CSR build ----------------
__global__ void k_zero() {
    int i = blockIdx.x * blockDim.x + threadIdx.x;
    if (i < NN) g_cnt[i] = 0;
}

__global__ void k_count(const int* __restrict__ dst) {
    int e = blockIdx.x * blockDim.x + threadIdx.x;
    if (e < EE) atomicAdd(&g_cnt[dst[e]], 1);
}

__global__ __launch_bounds__(1024) void k_scan() {
    __shared__ int sums[1024];
    const int CH = 5;                 // ceil(5000/1024)
    int t = threadIdx.x;
    int base = t * CH;
    int local[CH];
    int s = 0;
#pragma unroll
    for (int j = 0; j < CH; j++) {
        int idx = base + j;
        int c = (idx < NN) ? g_cnt[idx] : 0;
        local[j] = s;
        s += c;
    }
    sums[t] = s;
    __syncthreads();
    for (int off = 1; off < 1024; off <<= 1) {
        int v = (t >= off) ? sums[t - off] : 0;
        __syncthreads();
        sums[t] += v;
        __syncthreads();
    }
    int pre = (t > 0) ? sums[t - 1] : 0;
#pragma unroll
    for (int j = 0; j < CH; j++) {
        int idx = base + j;
        if (idx < NN) {
            g_off[idx] = pre + local[j];
            g_cur[idx] = pre + local[j];
        }
    }
    if (t == 0) g_off[NN] = sums[1023];
}

__global__ void k_scatter(const int* __restrict__ src, const int* __restrict__ dst) {
    int e = blockIdx.x * blockDim.x + threadIdx.x;
    if (e < EE) {
        int d = dst[e];
        int pos = atomicAdd(&g_cur[d], 1);
        g_eidx[pos] = e;
        g_esrc[pos] = src[e];
    }
}

// ---------------- phase 1: per-edge MLP + einsum -> ex = exp(lrelu(alpha)) --
// EPB edges per block, one warp per edge.
__global__ __launch_bounds__(EPB * 32) void k_edge(
    const float* __restrict__ state, const float* __restrict__ feature,
    const float* __restrict__ dist,
    const float* __restrict__ w1, const float* __restrict__ b1,
    const float* __restrict__ w2, const float* __restrict__ b2,
    const float* __restrict__ w3, const float* __restrict__ b3,
    const int* __restrict__ src, const int* __restrict__ dst)
{
    __shared__ float s_ef[EPB][104];
    __shared__ float s_h1[EPB][16];
    __shared__ float s_h2[EPB][4];
    __shared__ float s_sT[EPB][64 * 20];   // s transposed [k][b], pad 20
    __shared__ float s_W[EPB][2048];       // W [k=64][h=32]

    int w    = threadIdx.x >> 5;
    int lane = threadIdx.x & 31;
    int e    = blockIdx.x * EPB + w;
    if (e >= EE) return;

    int sn = src[e], dn = dst[e];

    // efeat = [feature[src](47), feature[dst](47), dist(2)]
    for (int i = lane; i < 96; i += 32) {
        float v;
        if (i < FEAT)          v = feature[(size_t)sn * FEAT + i];
        else if (i < 2 * FEAT) v = feature[(size_t)dn * FEAT + (i - FEAT)];
        else                   v = dist[(size_t)e * 2 + (i - 2 * FEAT)];
        s_ef[w][i] = v;
    }

    // gather s = [state[src], state[dst]] stored transposed: s_T[k][b]
    for (int idx = lane; idx < BB * 64; idx += 32) {
        int b = idx >> 6, k = idx & 63;
        float v = (k < HH) ? state[(size_t)sn * BH + b * HH + k]
                           : state[(size_t)dn * BH + b * HH + (k - HH)];
        s_sT[w][k * 20 + b] = v;
    }
    __syncwarp();

    // h1 = sigmoid(efeat @ w1 + b1)   [16]
    if (lane < 16) {
        float acc = b1[lane];
#pragma unroll 8
        for (int i = 0; i < 96; i++)
            acc = fmaf(s_ef[w][i], w1[i * 16 + lane], acc);
        s_h1[w][lane] = sigmoidf(acc);
    }
    __syncwarp();

    // h2 = sigmoid(h1 @ w2 + b2)   [2]
    if (lane < 2) {
        float acc = b2[lane];
#pragma unroll
        for (int j = 0; j < 16; j++)
            acc = fmaf(s_h1[w][j], w2[j * 2 + lane], acc);
        s_h2[w][lane] = sigmoidf(acc);
    }
    __syncwarp();

    // W = sigmoid(h2 @ w3 + b3)  -> 2048 values = [k=64][h=32]
    {
        float a0 = s_h2[w][0], a1 = s_h2[w][1];
        const float4* w30 = (const float4*)w3;             // row 0 (2048)
        const float4* w31 = (const float4*)(w3 + 2048);    // row 1 (2048)
        const float4* b34 = (const float4*)b3;
#pragma unroll
        for (int t = 0; t < 16; t++) {
            int q = t * 32 + lane;    // float4 index over 512
            float4 u = w30[q], v = w31[q], bb = b34[q];
            float4 r;
            r.x = sigmoidf(fmaf(a0, u.x, fmaf(a1, v.x, bb.x)));
            r.y = sigmoidf(fmaf(a0, u.y, fmaf(a1, v.y, bb.y)));
            r.z = sigmoidf(fmaf(a0, u.z, fmaf(a1, v.z, bb.z)));
            r.w = sigmoidf(fmaf(a0, u.w, fmaf(a1, v.w, bb.w)));
            *(float4*)&s_W[w][q * 4] = r;
        }
    }
    __syncwarp();

    // einsum alpha[b][h] = sum_k s[b][k] * W[k][h]; 4b x 4h per lane
    int b0 = (lane >> 3) * 4;
    int h0 = (lane & 7) * 4;
    float acc[4][4];
#pragma unroll
    for (int i = 0; i < 4; i++)
#pragma unroll
        for (int j = 0; j < 4; j++) acc[i][j] = 0.f;

#pragma unroll 4
    for (int k = 0; k < 64; k++) {
        float4 sv = *(const float4*)&s_sT[w][k * 20 + b0];
        float4 wv = *(const float4*)&s_W[w][k * 32 + h0];
        acc[0][0] = fmaf(sv.x, wv.x, acc[0][0]);
        acc[0][1] = fmaf(sv.x, wv.y, acc[0][1]);
        acc[0][2] = fmaf(sv.x, wv.z, acc[0][2]);
        acc[0][3] = fmaf(sv.x, wv.w, acc[0][3]);
        acc[1][0] = fmaf(sv.y, wv.x, acc[1][0]);
        acc[1][1] = fmaf(sv.y, wv.y, acc[1][1]);
        acc[1][2] = fmaf(sv.y, wv.z, acc[1][2]);
        acc[1][3] = fmaf(sv.y, wv.w, acc[1][3]);
        acc[2][0] = fmaf(sv.z, wv.x, acc[2][0]);
        acc[2][1] = fmaf(sv.z, wv.y, acc[2][1]);
        acc[2][2] = fmaf(sv.z, wv.z, acc[2][2]);
        acc[2][3] = fmaf(sv.z, wv.w, acc[2][3]);
        acc[3][0] = fmaf(sv.w, wv.x, acc[3][0]);
        acc[3][1] = fmaf(sv.w, wv.y, acc[3][1]);
        acc[3][2] = fmaf(sv.w, wv.z, acc[3][2]);
        acc[3][3] = fmaf(sv.w, wv.w, acc[3][3]);
    }

    // write ex = exp(leaky_relu(alpha))  (softmax shift-free: |alpha| < ~30)
    float* outp = g_ex + (size_t)e * BH;
#pragma unroll
    for (int i = 0; i < 4; i++) {
        float4 r;
        r.x = __expf(lrelu(acc[i][0]));
        r.y = __expf(lrelu(acc[i][1]));
        r.z = __expf(lrelu(acc[i][2]));
        r.w = __expf(lrelu(acc[i][3]));
        *(float4*)&outp[(b0 + i) * HH + h0] = r;
    }
}

// ---------------- phase 2: single-pass segment softmax + aggregate ----------
// block per node, thread per (b,h). a = (sum ex*state[src]) / (sum ex).
__global__ __launch_bounds__(512) void k_node(
    const float* __restrict__ state, const float* __restrict__ weight,
    float* __restrict__ out)
{
    int n = blockIdx.x;
    int t = threadIdx.x;   // (b,h) flat
    int beg = g_off[n], end = g_off[n + 1];

    float den = 0.f, num = 0.f;
    for (int i = beg; i < end; i++) {
        int e = g_eidx[i];
        int s = g_esrc[i];
        float ex = g_ex[(size_t)e * BH + t];
        den += ex;
        num = fmaf(ex, state[(size_t)s * BH + t], num);
    }
    float sw = 1.f / (1.f + __expf(-weight[0]));
    float a = (den > 0.f) ? (num / den) * sw : 0.f;
    out[(size_t)n * BH + t] = fmaxf(a, 0.f);
}

// ---------------- launcher ----------------
extern "C" void kernel_launch(void* const* d_in, const int* in_sizes, int n_in,
                              void* d_out, int out_size)
{
    const float* state   = (const float*)d_in[0];
    const float* feature = (const float*)d_in[1];
    const float* dist    = (const float*)d_in[2];
    const float* w1      = (const float*)d_in[3];
    const float* b1      = (const float*)d_in[4];
    const float* w2      = (const float*)d_in[5];
    const float* b2      = (const float*)d_in[6];
    const float* w3      = (const float*)d_in[7];
    const float* b3      = (const float*)d_in[8];
    const float* weight  = (const float*)d_in[9];
    const int*   src     = (const int*)d_in[10];
    const int*   dst     = (const int*)d_in[11];
    float*       out     = (float*)d_out;

    k_zero<<<(NN + 255) / 256, 256>>>();
    k_count<<<(EE + 255) / 256, 256>>>(dst);
    k_scan<<<1, 1024>>>();
    k_scatter<<<(EE + 255) / 256, 256>>>(src, dst);
    k_edge<<<(EE + EPB - 1) / EPB, EPB * 32>>>(state, feature, dist,
                                               w1, b1, w2, b2, w3, b3, src, dst);
    k_node<<<NN, 512>>>(state, weight, out);
}

// round 9
// speedup vs baseline: 1.5419x; 1.5419x over previous
#include <cuda_runtime.h>

#define NN   5000
#define EE   80000
#define HH   32
#define BB   16
#define BH   512      // B*H
#define FEAT 47
#define EPB  4        // edges per block (1 warp each); EE % EPB == 0

// ---- scratch (static __device__: allocation-free per harness rules) ----
__device__ float g_ex[(size_t)EE * BH];      // exp(alpha) rows in CSR (dst-sorted) order
__device__ int   g_cnt[NN];                  // zero-initialized at load; re-zeroed in k_scatter
__device__ int   g_off[NN + 1];
__device__ int   g_cur[NN];
__device__ int   g_pos[EE];                  // edge-id -> CSR slot
__device__ int   g_esrc[EE];                 // CSR-ordered src node ids

__device__ __forceinline__ float sigmoidf(float x) {
    float e = __expf(x);
    return __fdividef(e, 1.f + e);           // MUFU.EX2 + MUFU.RCP, no div.rn
}
__device__ __forceinline__ float lrelu(float x) {
    return x > 0.f ? x : 0.01f * x;
}

// ---- packed f32x2 helpers (sm_100+: SASS FFMA2, IEEE-exact per lane) ----
__device__ __forceinline__ unsigned long long splat2(float x) {
    unsigned long long r;
    unsigned u = __float_as_uint(x);
    asm("mov.b64 %0, {%1, %1};" : "=l"(r) : "r"(u));
    return r;
}
__device__ __forceinline__ unsigned long long fma2(unsigned long long a,
                                                   unsigned long long b,
                                                   unsigned long long c) {
    unsigned long long d;
    asm("fma.rn.f32x2 %0, %1, %2, %3;" : "=l"(d) : "l"(a), "l"(b), "l"(c));
    return d;
}
__device__ __forceinline__ float2 unpack2(unsigned long long v) {
    unsigned lo, hi;
    asm("mov.b64 {%0, %1}, %2;" : "=r"(lo), "=r"(hi) : "l"(v));
    float2 f;
    f.x = __uint_as_float(lo);
    f.y = __uint_as_float(hi);
    return f;
}

// ---------------- CSR build ----------------
__global__ void k_count(const int* __restrict__ dst) {
    int e = blockIdx.x * blockDim.x + threadIdx.x;
    if (e < EE) atomicAdd(&g_cnt[dst[e]], 1);
}

__global__ __launch_bounds__(1024) void k_scan() {
    __shared__ int sums[1024];
    const int CH = 5;                 // ceil(5000/1024)
    int t = threadIdx.x;
    int base = t * CH;
    int local[CH];
    int s = 0;
#pragma unroll
    for (int j = 0; j < CH; j++) {
        int idx = base + j;
        int c = (idx < NN) ? g_cnt[idx] : 0;
        local[j] = s;
        s += c;
    }
    sums[t] = s;
    __syncthreads();
    for (int off = 1; off < 1024; off <<= 1) {
        int v = (t >= off) ? sums[t - off] : 0;
        __syncthreads();
        sums[t] += v;
        __syncthreads();
    }
    int pre = (t > 0) ? sums[t - 1] : 0;
#pragma unroll
    for (int j = 0; j < CH; j++) {
        int idx = base + j;
        if (idx < NN) {
            g_off[idx] = pre + local[j];
            g_cur[idx] = pre + local[j];
        }
    }
    if (t == 0) g_off[NN] = sums[1023];
}

__global__ void k_scatter(const int* __restrict__ src, const int* __restrict__ dst) {
    int e = blockIdx.x * blockDim.x + threadIdx.x;
    if (e < EE) {
        int d = dst[e];
        int pos = atomicAdd(&g_cur[d], 1);
        g_pos[e]    = pos;     // edge -> CSR slot (k_edge writes ex there)
        g_esrc[pos] = src[e];
    }
    // re-zero g_cnt for the next graph replay (nothing reads it until then)
    if (e < NN) g_cnt[e] = 0;
}

// ---------------- phase 1: per-edge MLP + einsum -> ex = exp(lrelu(alpha)) --
// EPB edges per block, one warp per edge; W-generation is block-cooperative
// (each warp covers 1/EPB of w3 ONCE for all EPB edges -> w3 L1 traffic / EPB).
// ex rows are written to CSR slots so phase 2 streams g_ex sequentially.
__global__ __launch_bounds__(EPB * 32) void k_edge(
    const float* __restrict__ state, const float* __restrict__ feature,
    const float* __restrict__ dist,
    const float* __restrict__ w1, const float* __restrict__ b1,
    const float* __restrict__ w2, const float* __restrict__ b2,
    const float* __restrict__ w3, const float* __restrict__ b3,
    const int* __restrict__ src, const int* __restrict__ dst)
{
    __shared__ __align__(16) float s_ef[EPB][104];
    __shared__ float s_h1[EPB][16];
    __shared__ float s_h2[EPB][4];
    __shared__ __align__(16) float s_sT[EPB][64 * 20];   // s transposed [k][b], pad 20
    __shared__ __align__(16) float s_W[EPB][2048];       // W [k=64][h=32]

    int w    = threadIdx.x >> 5;
    int lane = threadIdx.x & 31;
    int e    = blockIdx.x * EPB + w;     // EE % EPB == 0 -> always valid

    int sn = src[e], dn = dst[e];

    // efeat = [feature[src](47), feature[dst](47), dist(2)]
    for (int i = lane; i < 96; i += 32) {
        float v;
        if (i < FEAT)          v = feature[(size_t)sn * FEAT + i];
        else if (i < 2 * FEAT) v = feature[(size_t)dn * FEAT + (i - FEAT)];
        else                   v = dist[(size_t)e * 2 + (i - 2 * FEAT)];
        s_ef[w][i] = v;
    }

    // gather s = [state[src], state[dst]] stored transposed: s_T[k][b]
    for (int idx = lane; idx < BB * 64; idx += 32) {
        int b = idx >> 6, k = idx & 63;
        float v = (k < HH) ? state[(size_t)sn * BH + b * HH + k]
                           : state[(size_t)dn * BH + b * HH + (k - HH)];
        s_sT[w][k * 20 + b] = v;
    }
    __syncwarp();

    // h1 = sigmoid(efeat @ w1 + b1)   [16]
    if (lane < 16) {
        float acc = b1[lane];
#pragma unroll 8
        for (int i = 0; i < 96; i++)
            acc = fmaf(s_ef[w][i], w1[i * 16 + lane], acc);
        s_h1[w][lane] = sigmoidf(acc);
    }
    __syncwarp();

    // h2 = sigmoid(h1 @ w2 + b2)   [2]
    if (lane < 2) {
        float acc = b2[lane];
#pragma unroll
        for (int j = 0; j < 16; j++)
            acc = fmaf(s_h1[w][j], w2[j * 2 + lane], acc);
        s_h2[w][lane] = sigmoidf(acc);
    }
    __syncthreads();   // all h2 visible to all warps

    // W[e'] = sigmoid(h2[e'] @ w3 + b3) -> [k=64][h=32] per edge.
    // Cooperative: warp w handles float4-quarter [w*128, w*128+128) of 512,
    // loading w3/b3 ONCE and producing that slice for all EPB edges.
    {
        float a0[EPB], a1[EPB];
#pragma unroll
        for (int eL = 0; eL < EPB; eL++) { a0[eL] = s_h2[eL][0]; a1[eL] = s_h2[eL][1]; }

        const float4* w30 = (const float4*)w3;             // row 0 (2048 floats)
        const float4* w31 = (const float4*)(w3 + 2048);    // row 1 (2048 floats)
        const float4* b34 = (const float4*)b3;
#pragma unroll
        for (int t = 0; t < 4; t++) {
            int q = w * 128 + t * 32 + lane;   // float4 index over 512
            float4 u = w30[q], v = w31[q], bb = b34[q];
#pragma unroll
            for (int eL = 0; eL < EPB; eL++) {
                float4 r;
                r.x = sigmoidf(fmaf(a0[eL], u.x, fmaf(a1[eL], v.x, bb.x)));
                r.y = sigmoidf(fmaf(a0[eL], u.y, fmaf(a1[eL], v.y, bb.y)));
                r.z = sigmoidf(fmaf(a0[eL], u.z, fmaf(a1[eL], v.z, bb.z)));
                r.w = sigmoidf(fmaf(a0[eL], u.w, fmaf(a1[eL], v.w, bb.w)));
                *(float4*)&s_W[eL][q * 4] = r;
            }
        }
    }
    __syncthreads();   // full W for this block's edges ready

    // einsum alpha[b][h] = sum_k s[b][k] * W[k][h]; 4b x 4h per lane.
    // Packed along h: float4 W load reinterpreted as 2x f32x2 (zero pack cost),
    // s broadcast via mov.b64 splat; 8 FFMA2 per k-step instead of 16 FFMA.
    int b0 = (lane >> 3) * 4;
    int h0 = (lane & 7) * 4;
    unsigned long long acc2[4][2];
#pragma unroll
    for (int i = 0; i < 4; i++) { acc2[i][0] = 0ULL; acc2[i][1] = 0ULL; }

#pragma unroll 4
    for (int k = 0; k < 64; k++) {
        float4 sv = *(const float4*)&s_sT[w][k * 20 + b0];
        ulonglong2 wv = *(const ulonglong2*)&s_W[w][k * 32 + h0];  // {h0,h1},{h2,h3}
        unsigned long long s0 = splat2(sv.x);
        unsigned long long s1 = splat2(sv.y);
        unsigned long long s2 = splat2(sv.z);
        unsigned long long s3 = splat2(sv.w);
        acc2[0][0] = fma2(s0, wv.x, acc2[0][0]);
        acc2[0][1] = fma2(s0, wv.y, acc2[0][1]);
        acc2[1][0] = fma2(s1, wv.x, acc2[1][0]);
        acc2[1][1] = fma2(s1, wv.y, acc2[1][1]);
        acc2[2][0] = fma2(s2, wv.x, acc2[2][0]);
        acc2[2][1] = fma2(s2, wv.y, acc2[2][1]);
        acc2[3][0] = fma2(s3, wv.x, acc2[3][0]);
        acc2[3][1] = fma2(s3, wv.y, acc2[3][1]);
    }

    // write ex = exp(leaky_relu(alpha)) into CSR slot (shift-free: |alpha| < ~30)
    float* outp = g_ex + (size_t)g_pos[e] * BH;
#pragma unroll
    for (int i = 0; i < 4; i++) {
        float2 p0 = unpack2(acc2[i][0]);
        float2 p1 = unpack2(acc2[i][1]);
        float4 r;
        r.x = __expf(lrelu(p0.x));
        r.y = __expf(lrelu(p0.y));
        r.z = __expf(lrelu(p1.x));
        r.w = __expf(lrelu(p1.y));
        *(float4*)&outp[(b0 + i) * HH + h0] = r;
    }
}

// ---------------- phase 2: single-pass segment softmax + aggregate ----------
// block per node, thread per (b,h). a = (sum ex*state[src]) / (sum ex).
// g_ex is CSR-ordered: rows read SEQUENTIALLY (no eidx indirection).
// Unrolled by 2: MLP=2 on the streams to overlap DRAM latency.
__global__ __launch_bounds__(512) void k_node(
    const float* __restrict__ state, const float* __restrict__ weight,
    float* __restrict__ out)
{
    int n = blockIdx.x;
    int t = threadIdx.x;   // (b,h) flat
    int beg = g_off[n], end = g_off[n + 1];

    float den = 0.f, num = 0.f;
    int i = beg;
    for (; i + 1 < end; i += 2) {
        int s0 = g_esrc[i],     s1 = g_esrc[i + 1];
        float ex0 = g_ex[(size_t)i * BH + t];
        float ex1 = g_ex[(size_t)(i + 1) * BH + t];
        float st0 = state[(size_t)s0 * BH + t];
        float st1 = state[(size_t)s1 * BH + t];
        den += ex0;
        num = fmaf(ex0, st0, num);
        den += ex1;
        num = fmaf(ex1, st1, num);
    }
    if (i < end) {
        int s0 = g_esrc[i];
        float ex0 = g_ex[(size_t)i * BH + t];
        den += ex0;
        num = fmaf(ex0, state[(size_t)s0 * BH + t], num);
    }
    float sw = sigmoidf(weight[0]);
    float a = (den > 0.f) ? __fdividef(num, den) * sw : 0.f;
    out[(size_t)n * BH + t] = fmaxf(a, 0.f);
}

// ---------------- launcher ----------------
extern "C" void kernel_launch(void* const* d_in, const int* in_sizes, int n_in,
                              void* d_out, int out_size)
{
    const float* state   = (const float*)d_in[0];
    const float* feature = (const float*)d_in[1];
    const float* dist    = (const float*)d_in[2];
    const float* w1      = (const float*)d_in[3];
    const float* b1      = (const float*)d_in[4];
    const float* w2      = (const float*)d_in[5];
    const float* b2      = (const float*)d_in[6];
    const float* w3      = (const float*)d_in[7];
    const float* b3      = (const float*)d_in[8];
    const float* weight  = (const float*)d_in[9];
    const int*   src     = (const int*)d_in[10];
    const int*   dst     = (const int*)d_in[11];
    float*       out     = (float*)d_out;

    k_count<<<(EE + 255) / 256, 256>>>(dst);
    k_scan<<<1, 1024>>>();
    k_scatter<<<(EE + 255) / 256, 256>>>(src, dst);
    k_edge<<<EE / EPB, EPB * 32>>>(state, feature, dist,
                                   w1, b1, w2, b2, w3, b3, src, dst);
    k_node<<<NN, 512>>>(state, weight, out);
}

// round 14
// speedup vs baseline: 1.6799x; 1.0895x over previous
#include <cuda_runtime.h>

#define NN   5000
#define EE   80000
#define HH   32
#define BB   16
#define BH   512      // B*H
#define FEAT 47
#define EPB  4        // edges per block (1 warp each); EE % EPB == 0

// ---- scratch (static __device__: allocation-free per harness rules) ----
__device__ float g_ex[(size_t)EE * BH];      // exp(alpha) rows in CSR (dst-sorted) order
__device__ float g_stateT[(size_t)NN * BH];  // state transposed per node: [n][h][b]
__device__ int   g_cnt[NN];                  // zero-initialized at load; re-zeroed in k_scatter
__device__ int   g_off[NN + 1];
__device__ int   g_cur[NN];
__device__ int   g_pos[EE];                  // edge-id -> CSR slot
__device__ int   g_esrc[EE];                 // CSR-ordered src node ids

__device__ __forceinline__ float sigmoidf(float x) {
    float e = __expf(x);
    return __fdividef(e, 1.f + e);           // MUFU.EX2 + MUFU.RCP
}
// W-gen sigmoid: single MUFU via tanh.approx (abs err ~1e-5, safe vs 1e-3 gate)
__device__ __forceinline__ float sigmoid_fast(float x) {
    float t;
    asm("tanh.approx.f32 %0, %1;" : "=f"(t) : "f"(x * 0.5f));
    return fmaf(t, 0.5f, 0.5f);
}
__device__ __forceinline__ float lrelu(float x) {
    return x > 0.f ? x : 0.01f * x;
}

// ---- packed f32x2 helpers (sm_100+: SASS FFMA2, IEEE-exact per lane) ----
__device__ __forceinline__ unsigned long long splat2(float x) {
    unsigned long long r;
    unsigned u = __float_as_uint(x);
    asm("mov.b64 %0, {%1, %1};" : "=l"(r) : "r"(u));
    return r;
}
__device__ __forceinline__ unsigned long long fma2(unsigned long long a,
                                                   unsigned long long b,
                                                   unsigned long long c) {
    unsigned long long d;
    asm("fma.rn.f32x2 %0, %1, %2, %3;" : "=l"(d) : "l"(a), "l"(b), "l"(c));
    return d;
}
__device__ __forceinline__ float2 unpack2(unsigned long long v) {
    unsigned lo, hi;
    asm("mov.b64 {%0, %1}, %2;" : "=r"(lo), "=r"(hi) : "l"(v));
    float2 f;
    f.x = __uint_as_float(lo);
    f.y = __uint_as_float(hi);
    return f;
}

// ---------------- state transpose: stateT[n][h][b] = state[n][b][h] ----------
__global__ __launch_bounds__(512) void k_transpose(const float* __restrict__ state) {
    __shared__ float tile[BB * 33];          // [b][h] padded 33 vs 32
    int n = blockIdx.x;
    int t = threadIdx.x;
    int b_in = t >> 5, h_in = t & 31;
    tile[b_in * 33 + h_in] = state[(size_t)n * BH + t];   // coalesced read
    __syncthreads();
    int h_out = t >> 4, b_out = t & 15;
    g_stateT[(size_t)n * BH + t] = tile[b_out * 33 + h_out];  // coalesced write
}

// ---------------- CSR build ----------------
__global__ void k_count(const int* __restrict__ dst) {
    int e = blockIdx.x * blockDim.x + threadIdx.x;
    if (e < EE) atomicAdd(&g_cnt[dst[e]], 1);
}

__global__ __launch_bounds__(1024) void k_scan() {
    __shared__ int sums[1024];
    const int CH = 5;                 // ceil(5000/1024)
    int t = threadIdx.x;
    int base = t * CH;
    int local[CH];
    int s = 0;
#pragma unroll
    for (int j = 0; j < CH; j++) {
        int idx = base + j;
        int c = (idx < NN) ? g_cnt[idx] : 0;
        local[j] = s;
        s += c;
    }
    sums[t] = s;
    __syncthreads();
    for (int off = 1; off < 1024; off <<= 1) {
        int v = (t >= off) ? sums[t - off] : 0;
        __syncthreads();
        sums[t] += v;
        __syncthreads();
    }
    int pre = (t > 0) ? sums[t - 1] : 0;
#pragma unroll
    for (int j = 0; j < CH; j++) {
        int idx = base + j;
        if (idx < NN) {
            g_off[idx] = pre + local[j];
            g_cur[idx] = pre + local[j];
        }
    }
    if (t == 0) g_off[NN] = sums[1023];
}

__global__ void k_scatter(const int* __restrict__ src, const int* __restrict__ dst) {
    int e = blockIdx.x * blockDim.x + threadIdx.x;
    if (e < EE) {
        int d = dst[e];
        int pos = atomicAdd(&g_cur[d], 1);
        g_pos[e]    = pos;     // edge -> CSR slot (k_edge writes ex there)
        g_esrc[pos] = src[e];
    }
    // re-zero g_cnt for the next graph replay (nothing reads it until then)
    if (e < NN) g_cnt[e] = 0;
}

// ---------------- phase 1: per-edge MLP + einsum -> ex = exp(lrelu(alpha)) --
// EPB edges per block, one warp per edge; W-generation is block-cooperative.
// s gather reads pre-transposed stateT: LDG.128 coalesced + STS.128 at the
// bank floor (bank pattern 4*(5k+j) mod 32 is uniform).
__global__ __launch_bounds__(EPB * 32) void k_edge(
    const float* __restrict__ state, const float* __restrict__ feature,
    const float* __restrict__ dist,
    const float* __restrict__ w1, const float* __restrict__ b1,
    const float* __restrict__ w2, const float* __restrict__ b2,
    const float* __restrict__ w3, const float* __restrict__ b3,
    const int* __restrict__ src, const int* __restrict__ dst)
{
    __shared__ __align__(16) float s_ef[EPB][104];
    __shared__ float s_h1[EPB][16];
    __shared__ float s_h2[EPB][4];
    __shared__ __align__(16) float s_sT[EPB][64 * 20];   // s transposed [k][b], pad 20
    __shared__ __align__(16) float s_W[EPB][2048];       // W [k=64][h=32]

    int w    = threadIdx.x >> 5;
    int lane = threadIdx.x & 31;
    int e    = blockIdx.x * EPB + w;     // EE % EPB == 0 -> always valid

    int sn = src[e], dn = dst[e];

    // efeat = [feature[src](47), feature[dst](47), dist(2)]
    for (int i = lane; i < 96; i += 32) {
        float v;
        if (i < FEAT)          v = feature[(size_t)sn * FEAT + i];
        else if (i < 2 * FEAT) v = feature[(size_t)dn * FEAT + (i - FEAT)];
        else                   v = dist[(size_t)e * 2 + (i - 2 * FEAT)];
        s_ef[w][i] = v;
    }

    // gather s_T[k][b]: rows k<32 from stateT[sn], k>=32 from stateT[dn].
    // 256 float4s; per iteration kk-range is uniform (it<4 -> src node).
    {
        const float4* pS = (const float4*)(g_stateT + (size_t)sn * BH);
        const float4* pD = (const float4*)(g_stateT + (size_t)dn * BH);
#pragma unroll
        for (int it = 0; it < 8; it++) {
            int idx = it * 32 + lane;          // 0..255
            int kk  = idx >> 2, j = idx & 3;
            float4 v = (it < 4) ? pS[kk * 4 + j] : pD[(kk - 32) * 4 + j];
            *(float4*)&s_sT[w][kk * 20 + j * 4] = v;
        }
    }
    __syncwarp();

    // h1 = sigmoid(efeat @ w1 + b1)   [16]
    if (lane < 16) {
        float acc = b1[lane];
#pragma unroll 8
        for (int i = 0; i < 96; i++)
            acc = fmaf(s_ef[w][i], w1[i * 16 + lane], acc);
        s_h1[w][lane] = sigmoidf(acc);
    }
    __syncwarp();

    // h2 = sigmoid(h1 @ w2 + b2)   [2]
    if (lane < 2) {
        float acc = b2[lane];
#pragma unroll
        for (int j = 0; j < 16; j++)
            acc = fmaf(s_h1[w][j], w2[j * 2 + lane], acc);
        s_h2[w][lane] = sigmoidf(acc);
    }
    __syncthreads();   // all h2 visible to all warps

    // W[e'] = sigmoid(h2[e'] @ w3 + b3) -> [k=64][h=32] per edge.
    // Cooperative: warp w handles float4-quarter [w*128, w*128+128) of 512,
    // loading w3/b3 ONCE for all EPB edges. sigmoid_fast: 1 MUFU.
    {
        float a0[EPB], a1[EPB];
#pragma unroll
        for (int eL = 0; eL < EPB; eL++) { a0[eL] = s_h2[eL][0]; a1[eL] = s_h2[eL][1]; }

        const float4* w30 = (const float4*)w3;             // row 0 (2048 floats)
        const float4* w31 = (const float4*)(w3 + 2048);    // row 1 (2048 floats)
        const float4* b34 = (const float4*)b3;
#pragma unroll
        for (int t = 0; t < 4; t++) {
            int q = w * 128 + t * 32 + lane;   // float4 index over 512
            float4 u = w30[q], v = w31[q], bb = b34[q];
#pragma unroll
            for (int eL = 0; eL < EPB; eL++) {
                float4 r;
                r.x = sigmoid_fast(fmaf(a0[eL], u.x, fmaf(a1[eL], v.x, bb.x)));
                r.y = sigmoid_fast(fmaf(a0[eL], u.y, fmaf(a1[eL], v.y, bb.y)));
                r.z = sigmoid_fast(fmaf(a0[eL], u.z, fmaf(a1[eL], v.z, bb.z)));
                r.w = sigmoid_fast(fmaf(a0[eL], u.w, fmaf(a1[eL], v.w, bb.w)));
                *(float4*)&s_W[eL][q * 4] = r;
            }
        }
    }
    __syncthreads();   // full W for this block's edges ready

    // einsum alpha[b][h] = sum_k s[b][k] * W[k][h]; 4b x 4h per lane.
    // Packed along h: 8 FFMA2 per k-step.
    int b0 = (lane >> 3) * 4;
    int h0 = (lane & 7) * 4;
    unsigned long long acc2[4][2];
#pragma unroll
    for (int i = 0; i < 4; i++) { acc2[i][0] = 0ULL; acc2[i][1] = 0ULL; }

#pragma unroll 4
    for (int k = 0; k < 64; k++) {
        float4 sv = *(const float4*)&s_sT[w][k * 20 + b0];
        ulonglong2 wv = *(const ulonglong2*)&s_W[w][k * 32 + h0];  // {h0,h1},{h2,h3}
        unsigned long long s0 = splat2(sv.x);
        unsigned long long s1 = splat2(sv.y);
        unsigned long long s2 = splat2(sv.z);
        unsigned long long s3 = splat2(sv.w);
        acc2[0][0] = fma2(s0, wv.x, acc2[0][0]);
        acc2[0][1] = fma2(s0, wv.y, acc2[0][1]);
        acc2[1][0] = fma2(s1, wv.x, acc2[1][0]);
        acc2[1][1] = fma2(s1, wv.y, acc2[1][1]);
        acc2[2][0] = fma2(s2, wv.x, acc2[2][0]);
        acc2[2][1] = fma2(s2, wv.y, acc2[2][1]);
        acc2[3][0] = fma2(s3, wv.x, acc2[3][0]);
        acc2[3][1] = fma2(s3, wv.y, acc2[3][1]);
    }

    // write ex = exp(leaky_relu(alpha)) into CSR slot (shift-free: |alpha| < ~30)
    float* outp = g_ex + (size_t)g_pos[e] * BH;
#pragma unroll
    for (int i = 0; i < 4; i++) {
        float2 p0 = unpack2(acc2[i][0]);
        float2 p1 = unpack2(acc2[i][1]);
        float4 r;
        r.x = __expf(lrelu(p0.x));
        r.y = __expf(lrelu(p0.y));
        r.z = __expf(lrelu(p1.x));
        r.w = __expf(lrelu(p1.y));
        *(float4*)&outp[(b0 + i) * HH + h0] = r;
    }
}

// ---------------- phase 2: single-pass segment softmax + aggregate ----------
// block per node, thread per (b,h). g_ex CSR-ordered -> sequential stream.
__global__ __launch_bounds__(512) void k_node(
    const float* __restrict__ state, const float* __restrict__ weight,
    float* __restrict__ out)
{
    int n = blockIdx.x;
    int t = threadIdx.x;   // (b,h) flat
    int beg = g_off[n], end = g_off[n + 1];

    float den = 0.f, num = 0.f;
    int i = beg;
    for (; i + 1 < end; i += 2) {
        int s0 = g_esrc[i],     s1 = g_esrc[i + 1];
        float ex0 = g_ex[(size_t)i * BH + t];
        float ex1 = g_ex[(size_t)(i + 1) * BH + t];
        float st0 = state[(size_t)s0 * BH + t];
        float st1 = state[(size_t)s1 * BH + t];
        den += ex0;
        num = fmaf(ex0, st0, num);
        den += ex1;
        num = fmaf(ex1, st1, num);
    }
    if (i < end) {
        int s0 = g_esrc[i];
        float ex0 = g_ex[(size_t)i * BH + t];
        den += ex0;
        num = fmaf(ex0, state[(size_t)s0 * BH + t], num);
    }
    float sw = sigmoidf(weight[0]);
    float a = (den > 0.f) ? __fdividef(num, den) * sw : 0.f;
    out[(size_t)n * BH + t] = fmaxf(a, 0.f);
}

// ---------------- launcher ----------------
extern "C" void kernel_launch(void* const* d_in, const int* in_sizes, int n_in,
                              void* d_out, int out_size)
{
    const float* state   = (const float*)d_in[0];
    const float* feature = (const float*)d_in[1];
    const float* dist    = (const float*)d_in[2];
    const float* w1      = (const float*)d_in[3];
    const float* b1      = (const float*)d_in[4];
    const float* w2      = (const float*)d_in[5];
    const float* b2      = (const float*)d_in[6];
    const float* w3      = (const float*)d_in[7];
    const float* b3      = (const float*)d_in[8];
    const float* weight  = (const float*)d_in[9];
    const int*   src     = (const int*)d_in[10];
    const int*   dst     = (const int*)d_in[11];
    float*       out     = (float*)d_out;

    k_transpose<<<NN, 512>>>(state);
    k_count<<<(EE + 255) / 256, 256>>>(dst);
    k_scan<<<1, 1024>>>();
    k_scatter<<<(EE + 255) / 256, 256>>>(src, dst);
    k_edge<<<EE / EPB, EPB * 32>>>(state, feature, dist,
                                   w1, b1, w2, b2, w3, b3, src, dst);
    k_node<<<NN, 512>>>(state, weight, out);
}

// round 15
// speedup vs baseline: 1.8936x; 1.1272x over previous
#include <cuda_runtime.h>

#define NN   5000
#define EE   80000
#define HH   32
#define BB   16
#define BH   512      // B*H
#define FEAT 47
#define EPB  4        // edges per block (1 warp each); EE % EPB == 0

// ---- scratch (static __device__: allocation-free per harness rules) ----
__device__ float g_ex[(size_t)EE * BH];      // exp(alpha) rows in CSR (dst-sorted) order
__device__ float g_stateT[(size_t)NN * BH];  // state transposed per node: [n][h][b]
__device__ int   g_cnt[NN];                  // zero-initialized at load; re-zeroed in k_scatter
__device__ int   g_off[NN + 1];
__device__ int   g_cur[NN];
__device__ int   g_pos[EE];                  // edge-id -> CSR slot
__device__ int   g_esrc[EE];                 // CSR-ordered src node ids

__device__ __forceinline__ float sigmoidf(float x) {
    float e = __expf(x);
    return __fdividef(e, 1.f + e);           // MUFU.EX2 + MUFU.RCP
}
// W-gen sigmoid: single MUFU via tanh.approx (measured: no rel_err impact)
__device__ __forceinline__ float sigmoid_fast(float x) {
    float t;
    asm("tanh.approx.f32 %0, %1;" : "=f"(t) : "f"(x * 0.5f));
    return fmaf(t, 0.5f, 0.5f);
}
__device__ __forceinline__ float lrelu(float x) {
    return x > 0.f ? x : 0.01f * x;
}

// ---- packed f32x2 helpers (sm_100+: SASS FFMA2, IEEE-exact per lane) ----
__device__ __forceinline__ unsigned long long splat2(float x) {
    unsigned long long r;
    unsigned u = __float_as_uint(x);
    asm("mov.b64 %0, {%1, %1};" : "=l"(r) : "r"(u));
    return r;
}
__device__ __forceinline__ unsigned long long fma2(unsigned long long a,
                                                   unsigned long long b,
                                                   unsigned long long c) {
    unsigned long long d;
    asm("fma.rn.f32x2 %0, %1, %2, %3;" : "=l"(d) : "l"(a), "l"(b), "l"(c));
    return d;
}
__device__ __forceinline__ float2 unpack2(unsigned long long v) {
    unsigned lo, hi;
    asm("mov.b64 {%0, %1}, %2;" : "=r"(lo), "=r"(hi) : "l"(v));
    float2 f;
    f.x = __uint_as_float(lo);
    f.y = __uint_as_float(hi);
    return f;
}

// -------- fused: state transpose + dst-degree count (launch #1) ------------
// block n: stateT[n][h][b] = state[n][b][h]; first EE global threads count dst.
__global__ __launch_bounds__(512) void k_trans_count(
    const float* __restrict__ state, const int* __restrict__ dst)
{
    __shared__ float tile[BB * 33];          // [b][h] padded 33 vs 32
    int n = blockIdx.x;
    int t = threadIdx.x;

    int gid = n * 512 + t;
    if (gid < EE) atomicAdd(&g_cnt[dst[gid]], 1);

    int b_in = t >> 5, h_in = t & 31;
    tile[b_in * 33 + h_in] = state[(size_t)n * BH + t];   // coalesced read
    __syncthreads();
    int h_out = t >> 4, b_out = t & 15;
    g_stateT[(size_t)n * BH + t] = tile[b_out * 33 + h_out];  // coalesced write
}

__global__ __launch_bounds__(1024) void k_scan() {
    __shared__ int sums[1024];
    const int CH = 5;                 // ceil(5000/1024)
    int t = threadIdx.x;
    int base = t * CH;
    int local[CH];
    int s = 0;
#pragma unroll
    for (int j = 0; j < CH; j++) {
        int idx = base + j;
        int c = (idx < NN) ? g_cnt[idx] : 0;
        local[j] = s;
        s += c;
    }
    sums[t] = s;
    __syncthreads();
    for (int off = 1; off < 1024; off <<= 1) {
        int v = (t >= off) ? sums[t - off] : 0;
        __syncthreads();
        sums[t] += v;
        __syncthreads();
    }
    int pre = (t > 0) ? sums[t - 1] : 0;
#pragma unroll
    for (int j = 0; j < CH; j++) {
        int idx = base + j;
        if (idx < NN) {
            g_off[idx] = pre + local[j];
            g_cur[idx] = pre + local[j];
        }
    }
    if (t == 0) g_off[NN] = sums[1023];
}

__global__ void k_scatter(const int* __restrict__ src, const int* __restrict__ dst) {
    int e = blockIdx.x * blockDim.x + threadIdx.x;
    if (e < EE) {
        int d = dst[e];
        int pos = atomicAdd(&g_cur[d], 1);
        g_pos[e]    = pos;     // edge -> CSR slot (k_edge writes ex there)
        g_esrc[pos] = src[e];
    }
    // re-zero g_cnt for the next graph replay (nothing reads it until then)
    if (e < NN) g_cnt[e] = 0;
}

// ---------------- phase 1: per-edge MLP + einsum -> ex = exp(lrelu(alpha)) --
__global__ __launch_bounds__(EPB * 32) void k_edge(
    const float* __restrict__ state, const float* __restrict__ feature,
    const float* __restrict__ dist,
    const float* __restrict__ w1, const float* __restrict__ b1,
    const float* __restrict__ w2, const float* __restrict__ b2,
    const float* __restrict__ w3, const float* __restrict__ b3,
    const int* __restrict__ src, const int* __restrict__ dst)
{
    __shared__ __align__(16) float s_ef[EPB][104];
    __shared__ float s_h1[EPB][16];
    __shared__ float s_h2[EPB][4];
    __shared__ __align__(16) float s_sT[EPB][64 * 20];   // s transposed [k][b], pad 20
    __shared__ __align__(16) float s_W[EPB][2048];       // W [k=64][h=32]

    int w    = threadIdx.x >> 5;
    int lane = threadIdx.x & 31;
    int e    = blockIdx.x * EPB + w;     // EE % EPB == 0 -> always valid

    int sn = src[e], dn = dst[e];

    // efeat = [feature[src](47), feature[dst](47), dist(2)]
    for (int i = lane; i < 96; i += 32) {
        float v;
        if (i < FEAT)          v = feature[(size_t)sn * FEAT + i];
        else if (i < 2 * FEAT) v = feature[(size_t)dn * FEAT + (i - FEAT)];
        else                   v = dist[(size_t)e * 2 + (i - 2 * FEAT)];
        s_ef[w][i] = v;
    }

    // gather s_T[k][b]: rows k<32 from stateT[sn], k>=32 from stateT[dn].
    {
        const float4* pS = (const float4*)(g_stateT + (size_t)sn * BH);
        const float4* pD = (const float4*)(g_stateT + (size_t)dn * BH);
#pragma unroll
        for (int it = 0; it < 8; it++) {
            int idx = it * 32 + lane;          // 0..255
            int kk  = idx >> 2, j = idx & 3;
            float4 v = (it < 4) ? pS[kk * 4 + j] : pD[(kk - 32) * 4 + j];
            *(float4*)&s_sT[w][kk * 20 + j * 4] = v;
        }
    }
    __syncwarp();

    // h1 = sigmoid(efeat @ w1 + b1) [16] -- split across lane halves:
    // lane l (l<16) accumulates i in [0,48), lane l+16 accumulates [48,96);
    // combine with one shfl_xor. All 32 lanes active, chain halved.
    {
        int l    = lane & 15;
        int half = lane >> 4;
        float acc = half ? 0.f : b1[l];
        int i0 = half * 48;
#pragma unroll 8
        for (int i = i0; i < i0 + 48; i++)
            acc = fmaf(s_ef[w][i], w1[i * 16 + l], acc);
        acc += __shfl_xor_sync(0xFFFFFFFFu, acc, 16);
        if (lane < 16) s_h1[w][lane] = sigmoidf(acc);
    }
    __syncwarp();

    // h2 = sigmoid(h1 @ w2 + b2)   [2]
    if (lane < 2) {
        float acc = b2[lane];
#pragma unroll
        for (int j = 0; j < 16; j++)
            acc = fmaf(s_h1[w][j], w2[j * 2 + lane], acc);
        s_h2[w][lane] = sigmoidf(acc);
    }
    __syncthreads();   // all h2 visible to all warps

    // W[e'] = sigmoid(h2[e'] @ w3 + b3) -> [k=64][h=32] per edge.
    // Cooperative: warp w handles float4-quarter of 512 for all EPB edges.
    {
        float a0[EPB], a1[EPB];
#pragma unroll
        for (int eL = 0; eL < EPB; eL++) { a0[eL] = s_h2[eL][0]; a1[eL] = s_h2[eL][1]; }

        const float4* w30 = (const float4*)w3;             // row 0 (2048 floats)
        const float4* w31 = (const float4*)(w3 + 2048);    // row 1 (2048 floats)
        const float4* b34 = (const float4*)b3;
#pragma unroll
        for (int t = 0; t < 4; t++) {
            int q = w * 128 + t * 32 + lane;   // float4 index over 512
            float4 u = w30[q], v = w31[q], bb = b34[q];
#pragma unroll
            for (int eL = 0; eL < EPB; eL++) {
                float4 r;
                r.x = sigmoid_fast(fmaf(a0[eL], u.x, fmaf(a1[eL], v.x, bb.x)));
                r.y = sigmoid_fast(fmaf(a0[eL], u.y, fmaf(a1[eL], v.y, bb.y)));
                r.z = sigmoid_fast(fmaf(a0[eL], u.z, fmaf(a1[eL], v.z, bb.z)));
                r.w = sigmoid_fast(fmaf(a0[eL], u.w, fmaf(a1[eL], v.w, bb.w)));
                *(float4*)&s_W[eL][q * 4] = r;
            }
        }
    }
    __syncthreads();   // full W for this block's edges ready

    // einsum alpha[b][h] = sum_k s[b][k] * W[k][h]; 4b x 4h per lane.
    int b0 = (lane >> 3) * 4;
    int h0 = (lane & 7) * 4;
    unsigned long long acc2[4][2];
#pragma unroll
    for (int i = 0; i < 4; i++) { acc2[i][0] = 0ULL; acc2[i][1] = 0ULL; }

#pragma unroll 4
    for (int k = 0; k < 64; k++) {
        float4 sv = *(const float4*)&s_sT[w][k * 20 + b0];
        ulonglong2 wv = *(const ulonglong2*)&s_W[w][k * 32 + h0];  // {h0,h1},{h2,h3}
        unsigned long long s0 = splat2(sv.x);
        unsigned long long s1 = splat2(sv.y);
        unsigned long long s2 = splat2(sv.z);
        unsigned long long s3 = splat2(sv.w);
        acc2[0][0] = fma2(s0, wv.x, acc2[0][0]);
        acc2[0][1] = fma2(s0, wv.y, acc2[0][1]);
        acc2[1][0] = fma2(s1, wv.x, acc2[1][0]);
        acc2[1][1] = fma2(s1, wv.y, acc2[1][1]);
        acc2[2][0] = fma2(s2, wv.x, acc2[2][0]);
        acc2[2][1] = fma2(s2, wv.y, acc2[2][1]);
        acc2[3][0] = fma2(s3, wv.x, acc2[3][0]);
        acc2[3][1] = fma2(s3, wv.y, acc2[3][1]);
    }

    // write ex = exp(leaky_relu(alpha)) into CSR slot (shift-free: |alpha| < ~30)
    float* outp = g_ex + (size_t)g_pos[e] * BH;
#pragma unroll
    for (int i = 0; i < 4; i++) {
        float2 p0 = unpack2(acc2[i][0]);
        float2 p1 = unpack2(acc2[i][1]);
        float4 r;
        r.x = __expf(lrelu(p0.x));
        r.y = __expf(lrelu(p0.y));
        r.z = __expf(lrelu(p1.x));
        r.w = __expf(lrelu(p1.y));
        *(float4*)&outp[(b0 + i) * HH + h0] = r;
    }
}

// ---------------- phase 2: single-pass segment softmax + aggregate ----------
__global__ __launch_bounds__(512) void k_node(
    const float* __restrict__ state, const float* __restrict__ weight,
    float* __restrict__ out)
{
    int n = blockIdx.x;
    int t = threadIdx.x;   // (b,h) flat
    int beg = g_off[n], end = g_off[n + 1];

    float den = 0.f, num = 0.f;
    int i = beg;
    for (; i + 1 < end; i += 2) {
        int s0 = g_esrc[i],     s1 = g_esrc[i + 1];
        float ex0 = g_ex[(size_t)i * BH + t];
        float ex1 = g_ex[(size_t)(i + 1) * BH + t];
        float st0 = state[(size_t)s0 * BH + t];
        float st1 = state[(size_t)s1 * BH + t];
        den += ex0;
        num = fmaf(ex0, st0, num);
        den += ex1;
        num = fmaf(ex1, st1, num);
    }
    if (i < end) {
        int s0 = g_esrc[i];
        float ex0 = g_ex[(size_t)i * BH + t];
        den += ex0;
        num = fmaf(ex0, state[(size_t)s0 * BH + t], num);
    }
    float sw = sigmoidf(weight[0]);
    float a = (den > 0.f) ? __fdividef(num, den) * sw : 0.f;
    out[(size_t)n * BH + t] = fmaxf(a, 0.f);
}

// ---------------- launcher ----------------
extern "C" void kernel_launch(void* const* d_in, const int* in_sizes, int n_in,
                              void* d_out, int out_size)
{
    const float* state   = (const float*)d_in[0];
    const float* feature = (const float*)d_in[1];
    const float* dist    = (const float*)d_in[2];
    const float* w1      = (const float*)d_in[3];
    const float* b1      = (const float*)d_in[4];
    const float* w2      = (const float*)d_in[5];
    const float* b2      = (const float*)d_in[6];
    const float* w3      = (const float*)d_in[7];
    const float* b3      = (const float*)d_in[8];
    const float* weight  = (const float*)d_in[9];
    const int*   src     = (const int*)d_in[10];
    const int*   dst     = (const int*)d_in[11];
    float*       out     = (float*)d_out;

    k_trans_count<<<NN, 512>>>(state, dst);   // launch 1
    k_scan<<<1, 1024>>>();                    // launch 2
    k_scatter<<<(EE + 255) / 256, 256>>>(src, dst);  // launch 3
    k_edge<<<EE / EPB, EPB * 32>>>(state, feature, dist,
                                   w1, b1, w2, b2, w3, b3, src, dst);  // launch 4 (profiled)
    k_node<<<NN, 512>>>(state, weight, out);  // launch 5
}

// round 17
// speedup vs baseline: 1.9195x; 1.0137x over previous
#include <cuda_runtime.h>

#define NN   5000
#define EE   80000
#define HH   32
#define BB   16
#define BH   512      // B*H
#define FEAT 47
#define EPB  4        // edges per block (1 warp each); EE % EPB == 0

// ---- scratch (static __device__: allocation-free per harness rules) ----
__device__ float g_ex[(size_t)EE * BH];      // exp(alpha) rows in CSR (dst-sorted) order
__device__ float g_stateT[(size_t)NN * BH];  // state transposed per node: [n][h][b]
__device__ int   g_cnt[NN];                  // zero-initialized at load; re-zeroed in k_scatter
__device__ int   g_off[NN + 1];
__device__ int   g_cur[NN];
__device__ int   g_pos[EE];                  // edge-id -> CSR slot
__device__ int   g_esrc[EE];                 // CSR-ordered src node ids

__device__ __forceinline__ float sigmoidf(float x) {
    float e = __expf(x);
    return __fdividef(e, 1.f + e);           // MUFU.EX2 + MUFU.RCP
}
// W-gen sigmoid: single MUFU via tanh.approx (measured: no rel_err impact)
__device__ __forceinline__ float sigmoid_fast(float x) {
    float t;
    asm("tanh.approx.f32 %0, %1;" : "=f"(t) : "f"(x * 0.5f));
    return fmaf(t, 0.5f, 0.5f);
}
__device__ __forceinline__ float lrelu(float x) {
    return x > 0.f ? x : 0.01f * x;
}

// ---- packed f32x2 helpers (sm_100+: SASS FFMA2, IEEE-exact per lane) ----
__device__ __forceinline__ unsigned long long splat2(float x) {
    unsigned long long r;
    unsigned u = __float_as_uint(x);
    asm("mov.b64 %0, {%1, %1};" : "=l"(r) : "r"(u));
    return r;
}
__device__ __forceinline__ unsigned long long fma2(unsigned long long a,
                                                   unsigned long long b,
                                                   unsigned long long c) {
    unsigned long long d;
    asm("fma.rn.f32x2 %0, %1, %2, %3;" : "=l"(d) : "l"(a), "l"(b), "l"(c));
    return d;
}
__device__ __forceinline__ float2 unpack2(unsigned long long v) {
    unsigned lo, hi;
    asm("mov.b64 {%0, %1}, %2;" : "=r"(lo), "=r"(hi) : "l"(v));
    float2 f;
    f.x = __uint_as_float(lo);
    f.y = __uint_as_float(hi);
    return f;
}

// -------- fused: state transpose + dst-degree count (launch #1) ------------
__global__ __launch_bounds__(512) void k_trans_count(
    const float* __restrict__ state, const int* __restrict__ dst)
{
    __shared__ float tile[BB * 33];          // [b][h] padded 33 vs 32
    int n = blockIdx.x;
    int t = threadIdx.x;

    int gid = n * 512 + t;
    if (gid < EE) atomicAdd(&g_cnt[dst[gid]], 1);

    int b_in = t >> 5, h_in = t & 31;
    tile[b_in * 33 + h_in] = state[(size_t)n * BH + t];   // coalesced read
    __syncthreads();
    int h_out = t >> 4, b_out = t & 15;
    g_stateT[(size_t)n * BH + t] = tile[b_out * 33 + h_out];  // coalesced write
}

__global__ __launch_bounds__(1024) void k_scan() {
    __shared__ int sums[1024];
    const int CH = 5;                 // ceil(5000/1024)
    int t = threadIdx.x;
    int base = t * CH;
    int local[CH];
    int s = 0;
#pragma unroll
    for (int j = 0; j < CH; j++) {
        int idx = base + j;
        int c = (idx < NN) ? g_cnt[idx] : 0;
        local[j] = s;
        s += c;
    }
    sums[t] = s;
    __syncthreads();
    for (int off = 1; off < 1024; off <<= 1) {
        int v = (t >= off) ? sums[t - off] : 0;
        __syncthreads();
        sums[t] += v;
        __syncthreads();
    }
    int pre = (t > 0) ? sums[t - 1] : 0;
#pragma unroll
    for (int j = 0; j < CH; j++) {
        int idx = base + j;
        if (idx < NN) {
            g_off[idx] = pre + local[j];
            g_cur[idx] = pre + local[j];
        }
    }
    if (t == 0) g_off[NN] = sums[1023];
}

__global__ void k_scatter(const int* __restrict__ src, const int* __restrict__ dst) {
    int e = blockIdx.x * blockDim.x + threadIdx.x;
    if (e < EE) {
        int d = dst[e];
        int pos = atomicAdd(&g_cur[d], 1);
        g_pos[e]    = pos;     // edge -> CSR slot (k_edge writes ex there)
        g_esrc[pos] = src[e];
    }
    // re-zero g_cnt for the next graph replay (nothing reads it until then)
    if (e < NN) g_cnt[e] = 0;
}

// ---------------- phase 1: per-edge MLP + einsum -> ex = exp(lrelu(alpha)) --
// Latency plan: gather LDGs issued at top into REGISTERS; h1/h2 (~600 cyc)
// run while they fly; STS after h2. W-gen double-buffers w3 across t-loop.
__global__ __launch_bounds__(EPB * 32, 4) void k_edge(
    const float* __restrict__ state, const float* __restrict__ feature,
    const float* __restrict__ dist,
    const float* __restrict__ w1, const float* __restrict__ b1,
    const float* __restrict__ w2, const float* __restrict__ b2,
    const float* __restrict__ w3, const float* __restrict__ b3,
    const int* __restrict__ src, const int* __restrict__ dst)
{
    __shared__ __align__(16) float s_ef[EPB][104];
    __shared__ float s_h1[EPB][16];
    __shared__ float s_h2[EPB][4];
    __shared__ __align__(16) float s_sT[EPB][64 * 20];   // s transposed [k][b], pad 20
    __shared__ __align__(16) float s_W[EPB][2048];       // W [k=64][h=32]

    int w    = threadIdx.x >> 5;
    int lane = threadIdx.x & 31;
    int e    = blockIdx.x * EPB + w;     // EE % EPB == 0 -> always valid

    int sn = src[e], dn = dst[e];

    // ---- issue gather LDGs (independent; consumed AFTER h2) ----
    float4 gv[8];
    {
        const float4* pS = (const float4*)(g_stateT + (size_t)sn * BH);
        const float4* pD = (const float4*)(g_stateT + (size_t)dn * BH);
#pragma unroll
        for (int it = 0; it < 8; it++) {
            int idx = it * 32 + lane;          // 0..255
            int kk  = idx >> 2, j = idx & 3;
            gv[it] = (it < 4) ? pS[kk * 4 + j] : pD[(kk - 32) * 4 + j];
        }
    }

    // efeat = [feature[src](47), feature[dst](47), dist(2)]
    for (int i = lane; i < 96; i += 32) {
        float v;
        if (i < FEAT)          v = feature[(size_t)sn * FEAT + i];
        else if (i < 2 * FEAT) v = feature[(size_t)dn * FEAT + (i - FEAT)];
        else                   v = dist[(size_t)e * 2 + (i - 2 * FEAT)];
        s_ef[w][i] = v;
    }
    __syncwarp();

    // h1 = sigmoid(efeat @ w1 + b1) [16] -- split across lane halves
    {
        int l    = lane & 15;
        int half = lane >> 4;
        float acc = half ? 0.f : b1[l];
        int i0 = half * 48;
#pragma unroll 8
        for (int i = i0; i < i0 + 48; i++)
            acc = fmaf(s_ef[w][i], w1[i * 16 + l], acc);
        acc += __shfl_xor_sync(0xFFFFFFFFu, acc, 16);
        if (lane < 16) s_h1[w][lane] = sigmoidf(acc);
    }
    __syncwarp();

    // h2 = sigmoid(h1 @ w2 + b2)   [2]
    if (lane < 2) {
        float acc = b2[lane];
#pragma unroll
        for (int j = 0; j < 16; j++)
            acc = fmaf(s_h1[w][j], w2[j * 2 + lane], acc);
        s_h2[w][lane] = sigmoidf(acc);
    }

    // ---- now store the (long since landed) gather data ----
    {
#pragma unroll
        for (int it = 0; it < 8; it++) {
            int idx = it * 32 + lane;
            int kk  = idx >> 2, j = idx & 3;
            *(float4*)&s_sT[w][kk * 20 + j * 4] = gv[it];
        }
    }
    __syncthreads();   // h2 visible to all warps (s_sT only needs warp scope)

    // W[e'] = sigmoid(h2[e'] @ w3 + b3) -> [k=64][h=32] per edge.
    // Cooperative quarter per warp; w3/b3 double-buffered across t.
    {
        float a0[EPB], a1[EPB];
#pragma unroll
        for (int eL = 0; eL < EPB; eL++) { a0[eL] = s_h2[eL][0]; a1[eL] = s_h2[eL][1]; }

        const float4* w30 = (const float4*)w3;             // row 0 (2048 floats)
        const float4* w31 = (const float4*)(w3 + 2048);    // row 1 (2048 floats)
        const float4* b34 = (const float4*)b3;

        int qbase = w * 128 + lane;
        float4 u = w30[qbase], v = w31[qbase], bb = b34[qbase];
#pragma unroll
        for (int t = 0; t < 4; t++) {
            float4 un, vn, bn;
            if (t < 3) {                       // prefetch next tile
                int qn = qbase + (t + 1) * 32;
                un = w30[qn]; vn = w31[qn]; bn = b34[qn];
            }
            int q = qbase + t * 32;
#pragma unroll
            for (int eL = 0; eL < EPB; eL++) {
                float4 r;
                r.x = sigmoid_fast(fmaf(a0[eL], u.x, fmaf(a1[eL], v.x, bb.x)));
                r.y = sigmoid_fast(fmaf(a0[eL], u.y, fmaf(a1[eL], v.y, bb.y)));
                r.z = sigmoid_fast(fmaf(a0[eL], u.z, fmaf(a1[eL], v.z, bb.z)));
                r.w = sigmoid_fast(fmaf(a0[eL], u.w, fmaf(a1[eL], v.w, bb.w)));
                *(float4*)&s_W[eL][q * 4] = r;
            }
            if (t < 3) { u = un; v = vn; bb = bn; }
        }
    }
    __syncthreads();   // full W for this block's edges ready

    // einsum alpha[b][h] = sum_k s[b][k] * W[k][h]; 4b x 4h per lane.
    int b0 = (lane >> 3) * 4;
    int h0 = (lane & 7) * 4;
    unsigned long long acc2[4][2];
#pragma unroll
    for (int i = 0; i < 4; i++) { acc2[i][0] = 0ULL; acc2[i][1] = 0ULL; }

#pragma unroll 4
    for (int k = 0; k < 64; k++) {
        float4 sv = *(const float4*)&s_sT[w][k * 20 + b0];
        ulonglong2 wv = *(const ulonglong2*)&s_W[w][k * 32 + h0];  // {h0,h1},{h2,h3}
        unsigned long long s0 = splat2(sv.x);
        unsigned long long s1 = splat2(sv.y);
        unsigned long long s2 = splat2(sv.z);
        unsigned long long s3 = splat2(sv.w);
        acc2[0][0] = fma2(s0, wv.x, acc2[0][0]);
        acc2[0][1] = fma2(s0, wv.y, acc2[0][1]);
        acc2[1][0] = fma2(s1, wv.x, acc2[1][0]);
        acc2[1][1] = fma2(s1, wv.y, acc2[1][1]);
        acc2[2][0] = fma2(s2, wv.x, acc2[2][0]);
        acc2[2][1] = fma2(s2, wv.y, acc2[2][1]);
        acc2[3][0] = fma2(s3, wv.x, acc2[3][0]);
        acc2[3][1] = fma2(s3, wv.y, acc2[3][1]);
    }

    // write ex = exp(leaky_relu(alpha)) into CSR slot (shift-free: |alpha| < ~30)
    float* outp = g_ex + (size_t)g_pos[e] * BH;
#pragma unroll
    for (int i = 0; i < 4; i++) {
        float2 p0 = unpack2(acc2[i][0]);
        float2 p1 = unpack2(acc2[i][1]);
        float4 r;
        r.x = __expf(lrelu(p0.x));
        r.y = __expf(lrelu(p0.y));
        r.z = __expf(lrelu(p1.x));
        r.w = __expf(lrelu(p1.y));
        *(float4*)&outp[(b0 + i) * HH + h0] = r;
    }
}

// ---------------- phase 2: single-pass segment softmax + aggregate ----------
// Unroll 4 with front-batched loads (MLP~8); summation order preserved.
__global__ __launch_bounds__(512) void k_node(
    const float* __restrict__ state, const float* __restrict__ weight,
    float* __restrict__ out)
{
    int n = blockIdx.x;
    int t = threadIdx.x;   // (b,h) flat
    int beg = g_off[n], end = g_off[n + 1];

    float den = 0.f, num = 0.f;
    int i = beg;
    for (; i + 3 < end; i += 4) {
        int s0 = g_esrc[i],     s1 = g_esrc[i + 1];
        int s2 = g_esrc[i + 2], s3 = g_esrc[i + 3];
        float ex0 = g_ex[(size_t)i * BH + t];
        float ex1 = g_ex[(size_t)(i + 1) * BH + t];
        float ex2 = g_ex[(size_t)(i + 2) * BH + t];
        float ex3 = g_ex[(size_t)(i + 3) * BH + t];
        float st0 = state[(size_t)s0 * BH + t];
        float st1 = state[(size_t)s1 * BH + t];
        float st2 = state[(size_t)s2 * BH + t];
        float st3 = state[(size_t)s3 * BH + t];
        den += ex0; num = fmaf(ex0, st0, num);
        den += ex1; num = fmaf(ex1, st1, num);
        den += ex2; num = fmaf(ex2, st2, num);
        den += ex3; num = fmaf(ex3, st3, num);
    }
    for (; i < end; i++) {
        int s0 = g_esrc[i];
        float ex0 = g_ex[(size_t)i * BH + t];
        den += ex0;
        num = fmaf(ex0, state[(size_t)s0 * BH + t], num);
    }
    float sw = sigmoidf(weight[0]);
    float a = (den > 0.f) ? __fdividef(num, den) * sw : 0.f;
    out[(size_t)n * BH + t] = fmaxf(a, 0.f);
}

// ---------------- launcher ----------------
extern "C" void kernel_launch(void* const* d_in, const int* in_sizes, int n_in,
                              void* d_out, int out_size)
{
    const float* state   = (const float*)d_in[0];
    const float* feature = (const float*)d_in[1];
    const float* dist    = (const float*)d_in[2];
    const float* w1      = (const float*)d_in[3];
    const float* b1      = (const float*)d_in[4];
    const float* w2      = (const float*)d_in[5];
    const float* b2      = (const float*)d_in[6];
    const float* w3      = (const float*)d_in[7];
    const float* b3      = (const float*)d_in[8];
    const float* weight  = (const float*)d_in[9];
    const int*   src     = (const int*)d_in[10];
    const int*   dst     = (const int*)d_in[11];
    float*       out     = (float*)d_out;

    k_trans_count<<<NN, 512>>>(state, dst);          // launch 1
    k_scan<<<1, 1024>>>();                           // launch 2
    k_scatter<<<(EE + 255) / 256, 256>>>(src, dst);  // launch 3
    k_edge<<<EE / EPB, EPB * 32>>>(state, feature, dist,
                                   w1, b1, w2, b2, w3, b3, src, dst);  // launch 4 (profiled)
    k_node<<<NN, 512>>>(state, weight, out);         // launch 5
}